// round 7
// baseline (speedup 1.0000x reference)
#include <cuda_runtime.h>
#include <math.h>

// Fused Linear(64->3) + F.normalize + cosine_similarity + acos(deg) + nan->0.
//
// R3 change vs R2: grid-stride over rows so the 24 W scalars are loaded ONCE
// per thread (register-resident) instead of once per row. R2 spent ~95% of
// L1tex wavefronts re-reading the 768B W matrix (L1=94.1%, DRAM only 49%).

#define EPS 1e-8f
#define RAD2DEG 57.2957795130823208768f  // 180/pi

__global__ __launch_bounds__(256, 8)
void net_kernel(const float* __restrict__ data,   // [N, 64]
                const float* __restrict__ lab,    // [N, 3]
                const float* __restrict__ W,      // [64, 3]
                const float* __restrict__ b,      // [3]
                float* __restrict__ out,          // [N]
                int N, int n_oct)
{
    const int gtid = blockIdx.x * blockDim.x + threadIdx.x;
    const int oct  = gtid >> 3;        // octet id = starting row
    const int sub  = gtid & 7;         // which 8-float chunk of a row

    // ---- W/b: loaded ONCE, live in registers across all rows ----
    const int kbase = sub << 3;
    float w0[8], w1[8], w2[8];
#pragma unroll
    for (int j = 0; j < 8; ++j) {
        const float* wr = W + (kbase + j) * 3;
        w0[j] = __ldg(wr + 0);
        w1[j] = __ldg(wr + 1);
        w2[j] = __ldg(wr + 2);
    }
    const float b0 = __ldg(b + 0);
    const float b1 = __ldg(b + 1);
    const float b2 = __ldg(b + 2);

    // Grid-stride over rows. Loop condition is warp-uniform via __any_sync so
    // the shfl_xor reductions always run fully converged; invalid lanes clamp
    // their load address and suppress the store.
    for (int row = oct; __any_sync(0xFFFFFFFFu, row < N); row += n_oct) {
        const bool valid = (row < N);
        const int  r     = valid ? row : (N - 1);

        // 2x LDG.128: warp = 4 consecutive rows = 1KB contiguous
        const float4* drow =
            reinterpret_cast<const float4*>(data + (size_t)r * 64) + (sub << 1);
        const float4 v0 = __ldg(drow + 0);
        const float4 v1 = __ldg(drow + 1);

        float a0 = 0.f, a1 = 0.f, a2 = 0.f;
        const float x[8] = { v0.x, v0.y, v0.z, v0.w, v1.x, v1.y, v1.z, v1.w };
#pragma unroll
        for (int j = 0; j < 8; ++j) {
            a0 = fmaf(x[j], w0[j], a0);
            a1 = fmaf(x[j], w1[j], a1);
            a2 = fmaf(x[j], w2[j], a2);
        }

        // octet reduction (xor 4/2/1 stays within the 8-lane group)
#pragma unroll
        for (int m = 4; m >= 1; m >>= 1) {
            a0 += __shfl_xor_sync(0xFFFFFFFFu, a0, m);
            a1 += __shfl_xor_sync(0xFFFFFFFFu, a1, m);
            a2 += __shfl_xor_sync(0xFFFFFFFFu, a2, m);
        }

        if (valid && sub == 0) {
            float p0 = a0 + b0;
            float p1 = a1 + b1;
            float p2 = a2 + b2;

            const float* lr = lab + (size_t)r * 3;
            float l0 = __ldg(lr + 0);
            float l1 = __ldg(lr + 1);
            float l2 = __ldg(lr + 2);

            // F.normalize(pred): pred / max(||pred||, eps)
            float pn2  = fmaf(p0, p0, fmaf(p1, p1, p2 * p2));
            float pnrm = sqrtf(pn2);
            float inv  = 1.0f / fmaxf(pnrm, EPS);

            // cosine_similarity(pred_n, lab)
            float dotraw = fmaf(p0, l0, fmaf(p1, l1, p2 * l2));
            float dot    = dotraw * inv;
            float na     = fmaxf(pnrm * inv, EPS);
            float ln2    = fmaf(l0, l0, fmaf(l1, l1, l2 * l2));
            float nb     = fmaxf(sqrtf(ln2), EPS);

            float cosv = dot / (na * nb);
            float loss = acosf(cosv) * RAD2DEG;
            if (isnan(loss)) loss = 0.0f;

            out[r] = loss;
        }
    }
}

extern "C" void kernel_launch(void* const* d_in, const int* in_sizes, int n_in,
                              void* d_out, int out_size)
{
    const float* data = (const float*)d_in[0];  // [N, 64]
    const float* lab  = (const float*)d_in[1];  // [N, 3]
    const float* W    = (const float*)d_in[2];  // [64, 3]
    const float* b    = (const float*)d_in[3];  // [3]
    float* out        = (float*)d_out;          // [N]

    const int N = out_size;

    // ~8 rows per octet: total_octets ≈ N/8
    const int threads        = 256;
    const int octs_per_block = threads / 8;                 // 32
    const int target_octs    = (N + 7) / 8;                 // ≈ N/8
    const int blocks         = (target_octs + octs_per_block - 1) / octs_per_block;
    const int n_oct          = blocks * octs_per_block;     // actual stride

    net_kernel<<<blocks, threads>>>(data, lab, W, b, out, N, n_oct);
}

// round 8
// speedup vs baseline: 1.2764x; 1.2764x over previous
#include <cuda_runtime.h>
#include <math.h>

// Fused Linear(64->3) + F.normalize + cosine_similarity + acos(deg) + nan->0.
//
// R7 change vs R3: line-aligned data chunking. Lane `sub` of an octet loads
// float4 #sub (bytes [0,128) of its row) and #sub+8 (bytes [128,256)), so each
// LDG.128 instruction touches exactly one 128B line per row (4 wavefronts per
// 512B = hardware minimum) instead of the old interleaved mapping that touched
// both lines from every instruction (2x wavefronts). W registers follow the
// new k-mapping: k in {4*sub..4*sub+3} u {32+4*sub..32+4*sub+3}.

#define EPS 1e-8f
#define RAD2DEG 57.2957795130823208768f  // 180/pi

__global__ __launch_bounds__(256, 6)
void net_kernel(const float* __restrict__ data,   // [N, 64]
                const float* __restrict__ lab,    // [N, 3]
                const float* __restrict__ W,      // [64, 3]
                const float* __restrict__ b,      // [3]
                float* __restrict__ out,          // [N]
                int N, int n_oct)
{
    const int gtid = blockIdx.x * blockDim.x + threadIdx.x;
    const int oct  = gtid >> 3;        // octet id = starting row
    const int sub  = gtid & 7;

    // ---- W/b once, register-resident. Thread's k-set:
    //      kA = 4*sub + j (j=0..3), kB = 32 + 4*sub + j ----
    float w0[8], w1[8], w2[8];
#pragma unroll
    for (int j = 0; j < 4; ++j) {
        const float* wa = W + (4 * sub + j) * 3;
        w0[j] = __ldg(wa + 0); w1[j] = __ldg(wa + 1); w2[j] = __ldg(wa + 2);
        const float* wb = W + (32 + 4 * sub + j) * 3;
        w0[4 + j] = __ldg(wb + 0); w1[4 + j] = __ldg(wb + 1); w2[4 + j] = __ldg(wb + 2);
    }
    const float b0 = __ldg(b + 0);
    const float b1 = __ldg(b + 1);
    const float b2 = __ldg(b + 2);

    // Grid-stride; warp covers 4 consecutive rows per iteration (coalesced
    // lab loads + stores). __any_sync keeps the shfl reductions converged.
    for (int row = oct; __any_sync(0xFFFFFFFFu, row < N); row += n_oct) {
        const bool valid = (row < N);
        const int  r     = valid ? row : (N - 1);

        // Line-aligned: inst 0 covers bytes [0,128) of each row (1 line/row),
        // inst 1 covers [128,256). 4 wavefronts per 512B instruction.
        const float4* d4 = reinterpret_cast<const float4*>(data + (size_t)r * 64);
        const float4 v0 = __ldg(d4 + sub);       // floats [4*sub, 4*sub+4)
        const float4 v1 = __ldg(d4 + sub + 8);   // floats [32+4*sub, ..+4)

        float a0 = 0.f, a1 = 0.f, a2 = 0.f;
        const float x[8] = { v0.x, v0.y, v0.z, v0.w, v1.x, v1.y, v1.z, v1.w };
#pragma unroll
        for (int j = 0; j < 8; ++j) {
            a0 = fmaf(x[j], w0[j], a0);
            a1 = fmaf(x[j], w1[j], a1);
            a2 = fmaf(x[j], w2[j], a2);
        }

        // octet butterfly reduction (xor 4/2/1 stays within the 8-lane group)
#pragma unroll
        for (int m = 4; m >= 1; m >>= 1) {
            a0 += __shfl_xor_sync(0xFFFFFFFFu, a0, m);
            a1 += __shfl_xor_sync(0xFFFFFFFFu, a1, m);
            a2 += __shfl_xor_sync(0xFFFFFFFFu, a2, m);
        }

        if (valid && sub == 0) {
            float p0 = a0 + b0;
            float p1 = a1 + b1;
            float p2 = a2 + b2;

            const float* lr = lab + (size_t)r * 3;
            float l0 = __ldg(lr + 0);
            float l1 = __ldg(lr + 1);
            float l2 = __ldg(lr + 2);

            // F.normalize(pred): pred / max(||pred||, eps)
            float pn2  = fmaf(p0, p0, fmaf(p1, p1, p2 * p2));
            float pnrm = sqrtf(pn2);
            float inv  = 1.0f / fmaxf(pnrm, EPS);

            // cosine_similarity(pred_n, lab)
            float dotraw = fmaf(p0, l0, fmaf(p1, l1, p2 * l2));
            float dot    = dotraw * inv;
            float na     = fmaxf(pnrm * inv, EPS);
            float ln2    = fmaf(l0, l0, fmaf(l1, l1, l2 * l2));
            float nb     = fmaxf(sqrtf(ln2), EPS);

            float cosv = dot / (na * nb);
            float loss = acosf(cosv) * RAD2DEG;
            if (isnan(loss)) loss = 0.0f;

            out[r] = loss;
        }
    }
}

extern "C" void kernel_launch(void* const* d_in, const int* in_sizes, int n_in,
                              void* d_out, int out_size)
{
    const float* data = (const float*)d_in[0];  // [N, 64]
    const float* lab  = (const float*)d_in[1];  // [N, 3]
    const float* W    = (const float*)d_in[2];  // [64, 3]
    const float* b    = (const float*)d_in[3];  // [3]
    float* out        = (float*)d_out;          // [N]

    const int N = out_size;

    // ~16 rows per octet
    const int threads        = 256;
    const int octs_per_block = threads / 8;                  // 32
    const int target_octs    = (N + 15) / 16;                // ~N/16
    const int blocks         = (target_octs + octs_per_block - 1) / octs_per_block;
    const int n_oct          = blocks * octs_per_block;

    net_kernel<<<blocks, threads>>>(data, lab, W, b, out, N, n_oct);
}

// round 9
// speedup vs baseline: 1.5456x; 1.2110x over previous
#include <cuda_runtime.h>
#include <math.h>

// Fused Linear(64->3) + F.normalize + cosine_similarity + acos(deg) + nan->0.
//
// R8 changes vs R7:
//  - 2 rows per octet per iteration: 4 independent LDG.128 in flight (MLP=4),
//    6 independent shfl butterfly chains, half the loop overhead per row.
//  - W loaded with 6 LDG.128 (W[12*sub..+12) is 16B-aligned) instead of 24
//    scalar LDGs (~18 L1 wavefronts one-time vs ~144).
//  - Epilogue split across lanes 0/1 of each octet (sums live in all lanes
//    after the butterfly), 2x epilogue parallelism.

#define EPS 1e-8f
#define RAD2DEG 57.2957795130823208768f  // 180/pi

__global__ __launch_bounds__(256)
void net_kernel(const float* __restrict__ data,   // [N, 64]
                const float* __restrict__ lab,    // [N, 3]
                const float* __restrict__ W,      // [64, 3]
                const float* __restrict__ b,      // [3]
                float* __restrict__ out,          // [N]
                int N, int n_pair)
{
    const int gtid = blockIdx.x * blockDim.x + threadIdx.x;
    const int oct  = gtid >> 3;   // octet id = row-pair index
    const int sub  = gtid & 7;

    // ---- W via 6 vector loads; thread's k-set: {4sub..4sub+3, 32+4sub..+3}.
    //      W floats [12*sub, 12*sub+12) = float4 idx [3*sub, 3*sub+3), and
    //      [96+12*sub, ...) = float4 idx [24+3*sub, ...). 48*sub bytes is
    //      16B-aligned, so these are clean LDG.128s.
    const float4* W4 = reinterpret_cast<const float4*>(W);
    const float4 wa0 = __ldg(W4 + 3 * sub + 0);
    const float4 wa1 = __ldg(W4 + 3 * sub + 1);
    const float4 wa2 = __ldg(W4 + 3 * sub + 2);
    const float4 wb0 = __ldg(W4 + 24 + 3 * sub + 0);
    const float4 wb1 = __ldg(W4 + 24 + 3 * sub + 1);
    const float4 wb2 = __ldg(W4 + 24 + 3 * sub + 2);

    float w0[8], w1[8], w2[8];
    w0[0]=wa0.x; w1[0]=wa0.y; w2[0]=wa0.z;   // k = 4sub+0
    w0[1]=wa0.w; w1[1]=wa1.x; w2[1]=wa1.y;   // k = 4sub+1
    w0[2]=wa1.z; w1[2]=wa1.w; w2[2]=wa2.x;   // k = 4sub+2
    w0[3]=wa2.y; w1[3]=wa2.z; w2[3]=wa2.w;   // k = 4sub+3
    w0[4]=wb0.x; w1[4]=wb0.y; w2[4]=wb0.z;   // k = 32+4sub+0
    w0[5]=wb0.w; w1[5]=wb1.x; w2[5]=wb1.y;   // k = 32+4sub+1
    w0[6]=wb1.z; w1[6]=wb1.w; w2[6]=wb2.x;   // k = 32+4sub+2
    w0[7]=wb2.y; w1[7]=wb2.z; w2[7]=wb2.w;   // k = 32+4sub+3

    const float bb0 = __ldg(b + 0);
    const float bb1 = __ldg(b + 1);
    const float bb2 = __ldg(b + 2);

    // Grid-stride over row PAIRS. Warp (4 octets) covers 8 consecutive rows.
    for (int p = oct; __any_sync(0xFFFFFFFFu, 2 * p < N); p += n_pair) {
        const int rA = 2 * p;
        const int rB = 2 * p + 1;
        const bool vA = (rA < N);
        const bool vB = (rB < N);
        const int cA = vA ? rA : (N - 1);
        const int cB = vB ? rB : (N - 1);

        // 4 independent line-aligned LDG.128s issued back-to-back (MLP=4).
        const float4* dA = reinterpret_cast<const float4*>(data + (size_t)cA * 64);
        const float4* dB = reinterpret_cast<const float4*>(data + (size_t)cB * 64);
        const float4 va0 = __ldg(dA + sub);
        const float4 va1 = __ldg(dA + sub + 8);
        const float4 vb0 = __ldg(dB + sub);
        const float4 vb1 = __ldg(dB + sub + 8);

        float sA0 = 0.f, sA1 = 0.f, sA2 = 0.f;
        float sB0 = 0.f, sB1 = 0.f, sB2 = 0.f;
        const float xA[8] = { va0.x, va0.y, va0.z, va0.w, va1.x, va1.y, va1.z, va1.w };
        const float xB[8] = { vb0.x, vb0.y, vb0.z, vb0.w, vb1.x, vb1.y, vb1.z, vb1.w };
#pragma unroll
        for (int j = 0; j < 8; ++j) {
            sA0 = fmaf(xA[j], w0[j], sA0);
            sA1 = fmaf(xA[j], w1[j], sA1);
            sA2 = fmaf(xA[j], w2[j], sA2);
            sB0 = fmaf(xB[j], w0[j], sB0);
            sB1 = fmaf(xB[j], w1[j], sB1);
            sB2 = fmaf(xB[j], w2[j], sB2);
        }

        // Butterfly over the octet: 6 independent chains, full ILP overlap.
#pragma unroll
        for (int m = 4; m >= 1; m >>= 1) {
            sA0 += __shfl_xor_sync(0xFFFFFFFFu, sA0, m);
            sA1 += __shfl_xor_sync(0xFFFFFFFFu, sA1, m);
            sA2 += __shfl_xor_sync(0xFFFFFFFFu, sA2, m);
            sB0 += __shfl_xor_sync(0xFFFFFFFFu, sB0, m);
            sB1 += __shfl_xor_sync(0xFFFFFFFFu, sB1, m);
            sB2 += __shfl_xor_sync(0xFFFFFFFFu, sB2, m);
        }

        // Sums live in all 8 lanes: lane 0 finishes row A, lane 1 row B.
        if (sub < 2) {
            const bool v = sub ? vB : vA;
            if (v) {
                const int r = sub ? cB : cA;
                float p0 = (sub ? sB0 : sA0) + bb0;
                float p1 = (sub ? sB1 : sA1) + bb1;
                float p2 = (sub ? sB2 : sA2) + bb2;

                const float* lr = lab + (size_t)r * 3;
                const float l0 = __ldg(lr + 0);
                const float l1 = __ldg(lr + 1);
                const float l2 = __ldg(lr + 2);

                // F.normalize(pred): pred / max(||pred||, eps)
                const float pn2  = fmaf(p0, p0, fmaf(p1, p1, p2 * p2));
                const float pnrm = sqrtf(pn2);
                const float inv  = 1.0f / fmaxf(pnrm, EPS);

                // cosine_similarity(pred_n, lab)
                const float dotraw = fmaf(p0, l0, fmaf(p1, l1, p2 * l2));
                const float dot    = dotraw * inv;
                const float na     = fmaxf(pnrm * inv, EPS);
                const float ln2    = fmaf(l0, l0, fmaf(l1, l1, l2 * l2));
                const float nb     = fmaxf(sqrtf(ln2), EPS);

                const float cosv = dot / (na * nb);
                float loss = acosf(cosv) * RAD2DEG;
                if (isnan(loss)) loss = 0.0f;

                out[r] = loss;
            }
        }
    }
}

extern "C" void kernel_launch(void* const* d_in, const int* in_sizes, int n_in,
                              void* d_out, int out_size)
{
    const float* data = (const float*)d_in[0];  // [N, 64]
    const float* lab  = (const float*)d_in[1];  // [N, 3]
    const float* W    = (const float*)d_in[2];  // [64, 3]
    const float* b    = (const float*)d_in[3];  // [3]
    float* out        = (float*)d_out;          // [N]

    const int N = out_size;

    // ~4 pair-iterations per octet (8 rows/octet)
    const int threads        = 256;
    const int octs_per_block = threads / 8;                  // 32
    const int pairs          = (N + 1) / 2;
    const int iters          = 4;
    const int blocks = (pairs + octs_per_block * iters - 1) / (octs_per_block * iters);
    const int n_pair = blocks * octs_per_block;

    net_kernel<<<blocks, threads>>>(data, lab, W, b, out, N, n_pair);
}